// round 13
// baseline (speedup 1.0000x reference)
#include <cuda_runtime.h>
#include <cuda_bf16.h>
#include <cstdint>

#define DIM    1024
#define HEADS  16
#define GROUPS 4
#define HG     (HEADS/GROUPS)
#define DHEAD  64
#define INNER  1024
#define KVDIM  512
#define BATCH  4
#define SEQ    2048
#define ROWS   (BATCH*SEQ)
#define LN_EPS 1e-6f
#define LOG2E  1.44269504088896f

// ---------------- scratch (__device__ globals, allocation-free) ----------------
__device__ __align__(16) __nv_bfloat16 g_xn_hi[ROWS*DIM];
__device__ __align__(16) __nv_bfloat16 g_xn_lo[ROWS*DIM];
__device__ __align__(16) float         g_q [ROWS*INNER];
__device__ __align__(16) float         g_kv[ROWS*KVDIM];
__device__ __align__(16) __nv_bfloat16 g_qh[ROWS*INNER];
__device__ __align__(16) __nv_bfloat16 g_ql[ROWS*INNER];
__device__ __align__(16) __nv_bfloat16 g_kh[BATCH*GROUPS*SEQ*DHEAD];
__device__ __align__(16) __nv_bfloat16 g_kl[BATCH*GROUPS*SEQ*DHEAD];
__device__ __align__(16) __nv_bfloat16 g_vh[BATCH*GROUPS*SEQ*DHEAD];  // row-major [bg][n][d]
__device__ __align__(16) __nv_bfloat16 g_vl[BATCH*GROUPS*SEQ*DHEAD];
__device__ __align__(16) __nv_bfloat16 g_oh[ROWS*INNER];
__device__ __align__(16) __nv_bfloat16 g_ol[ROWS*INNER];
__device__ __align__(16) __nv_bfloat16 g_wq_hi [INNER*DIM];   // [N,K]
__device__ __align__(16) __nv_bfloat16 g_wq_lo [INNER*DIM];
__device__ __align__(16) __nv_bfloat16 g_wkv_hi[KVDIM*DIM];
__device__ __align__(16) __nv_bfloat16 g_wkv_lo[KVDIM*DIM];
__device__ __align__(16) __nv_bfloat16 g_wo_hi [DIM*INNER];
__device__ __align__(16) __nv_bfloat16 g_wo_lo [DIM*INNER];

// ---------------- helpers ----------------
__device__ __forceinline__ uint32_t smem_u32(const void* p) {
    uint32_t a;
    asm("{ .reg .u64 t; cvta.to.shared.u64 t, %1; cvt.u32.u64 %0, t; }" : "=r"(a) : "l"(p));
    return a;
}
__device__ __forceinline__ void mma_bf16(float c[4], const uint32_t a[4],
                                         uint32_t b0, uint32_t b1) {
    asm volatile(
        "mma.sync.aligned.m16n8k16.row.col.f32.bf16.bf16.f32 "
        "{%0,%1,%2,%3}, {%4,%5,%6,%7}, {%8,%9}, {%0,%1,%2,%3};"
        : "+f"(c[0]), "+f"(c[1]), "+f"(c[2]), "+f"(c[3])
        : "r"(a[0]), "r"(a[1]), "r"(a[2]), "r"(a[3]), "r"(b0), "r"(b1));
}
__device__ __forceinline__ void ldsm_x4(uint32_t addr, uint32_t& r0, uint32_t& r1,
                                        uint32_t& r2, uint32_t& r3) {
    asm volatile("ldmatrix.sync.aligned.m8n8.x4.shared.b16 {%0,%1,%2,%3}, [%4];"
        : "=r"(r0), "=r"(r1), "=r"(r2), "=r"(r3) : "r"(addr));
}
__device__ __forceinline__ void ldsm_x4_t(uint32_t addr, uint32_t& r0, uint32_t& r1,
                                          uint32_t& r2, uint32_t& r3) {
    asm volatile("ldmatrix.sync.aligned.m8n8.x4.trans.shared.b16 {%0,%1,%2,%3}, [%4];"
        : "=r"(r0), "=r"(r1), "=r"(r2), "=r"(r3) : "r"(addr));
}
#define CP16(dst, src) \
    asm volatile("cp.async.cg.shared.global [%0], [%1], 16;" :: "r"(dst), "l"(src))
#define CP_COMMIT() asm volatile("cp.async.commit_group;" ::: "memory")
#define CP_WAIT(n)  asm volatile("cp.async.wait_group %0;" :: "n"(n) : "memory")

__device__ __forceinline__ float fexp2(float x) {
    float r;
    asm("ex2.approx.f32 %0, %1;" : "=f"(r) : "f"(x));
    return r;
}
__device__ __forceinline__ void split_bf16(float v, __nv_bfloat16& h, __nv_bfloat16& l) {
    h = __float2bfloat16(v);
    l = __float2bfloat16(v - __bfloat162float(h));
}
__device__ __forceinline__ uint32_t pack2_u32(__nv_bfloat16 a, __nv_bfloat16 b) {
    __nv_bfloat162 p(a, b);
    return *reinterpret_cast<uint32_t*>(&p);
}
__device__ __forceinline__ void split_pack2(float v0, float v1, uint32_t& hw, uint32_t& lw) {
    __nv_bfloat16 h0, l0, h1, l1;
    split_bf16(v0, h0, l0);
    split_bf16(v1, h1, l1);
    hw = pack2_u32(h0, h1);
    lw = pack2_u32(l0, l1);
}

// ---------------- input layernorm, emits bf16 hi/lo split ----------------
__global__ __launch_bounds__(256) void ln_kernel(const float* __restrict__ x,
                                                 const float* __restrict__ sc,
                                                 const float* __restrict__ bi) {
    int row = blockIdx.x;
    int t = threadIdx.x;
    const float4 a = reinterpret_cast<const float4*>(x)[row*(DIM/4) + t];
    float s  = a.x + a.y + a.z + a.w;
    float sq = a.x*a.x + a.y*a.y + a.z*a.z + a.w*a.w;
    #pragma unroll
    for (int o = 16; o > 0; o >>= 1) {
        s  += __shfl_xor_sync(0xffffffffu, s,  o);
        sq += __shfl_xor_sync(0xffffffffu, sq, o);
    }
    __shared__ float ws[8], wq[8];
    if ((t & 31) == 0) { ws[t >> 5] = s; wq[t >> 5] = sq; }
    __syncthreads();
    s = 0.f; sq = 0.f;
    #pragma unroll
    for (int i = 0; i < 8; i++) { s += ws[i]; sq += wq[i]; }
    float mean = s  * (1.f/DIM);
    float var  = sq * (1.f/DIM) - mean*mean;
    float rstd = rsqrtf(var + LN_EPS);
    float4 s4 = reinterpret_cast<const float4*>(sc)[t];
    float4 b4 = reinterpret_cast<const float4*>(bi)[t];
    float v[4];
    v[0] = (a.x - mean)*rstd*s4.x + b4.x;
    v[1] = (a.y - mean)*rstd*s4.y + b4.y;
    v[2] = (a.z - mean)*rstd*s4.z + b4.z;
    v[3] = (a.w - mean)*rstd*s4.w + b4.w;
    __nv_bfloat16 hi[4], lo[4];
    #pragma unroll
    for (int i = 0; i < 4; i++) split_bf16(v[i], hi[i], lo[i]);
    size_t base = (size_t)row * DIM + t * 4;
    *reinterpret_cast<__nv_bfloat162*>(g_xn_hi + base)     = __nv_bfloat162(hi[0], hi[1]);
    *reinterpret_cast<__nv_bfloat162*>(g_xn_hi + base + 2) = __nv_bfloat162(hi[2], hi[3]);
    *reinterpret_cast<__nv_bfloat162*>(g_xn_lo + base)     = __nv_bfloat162(lo[0], lo[1]);
    *reinterpret_cast<__nv_bfloat162*>(g_xn_lo + base + 2) = __nv_bfloat162(lo[2], lo[3]);
}

// ---------------- weight transpose + split: W[K,N] fp32 -> T[N,K] bf16 hi/lo ----------------
__global__ __launch_bounds__(256) void wconv_kernel(const float* __restrict__ W,
                                                    __nv_bfloat16* __restrict__ Thi,
                                                    __nv_bfloat16* __restrict__ Tlo,
                                                    int K, int N) {
    __shared__ float tile[32][33];
    int kb = blockIdx.y * 32, nb = blockIdx.x * 32;
    int tx = threadIdx.x & 31, ty = threadIdx.x >> 5;  // 32 x 8
    #pragma unroll
    for (int i = ty; i < 32; i += 8)
        tile[i][tx] = W[(size_t)(kb + i) * N + nb + tx];
    __syncthreads();
    #pragma unroll
    for (int i = ty; i < 32; i += 8) {
        float v = tile[tx][i];
        __nv_bfloat16 h, l;
        split_bf16(v, h, l);
        size_t idx = (size_t)(nb + i) * K + kb + tx;
        Thi[idx] = h;
        Tlo[idx] = l;
    }
}

// ---------------- warp-MMA split-bf16 GEMM (ldmatrix + cp.async 2-stage) ----------------
#define G_ROWB   80
#define G_ARR_B  (128*G_ROWB)
#define G_STAGE  (4*G_ARR_B)
#define G_SMEM   (2*G_STAGE)

__global__ __launch_bounds__(256, 2) void gemm_mma(const __nv_bfloat16* __restrict__ Ahi,
                                                   const __nv_bfloat16* __restrict__ Alo,
                                                   const __nv_bfloat16* __restrict__ Bhi,
                                                   const __nv_bfloat16* __restrict__ Blo,
                                                   float* __restrict__ C, int N, int K) {
    extern __shared__ char smg[];
    const uint32_t sb = smem_u32(smg);
    const int tid  = threadIdx.x;
    const int warp = tid >> 5, lane = tid & 31;
    const int wm = warp & 3, wn = warp >> 2;
    const int gi = lane >> 2, t = lane & 3;
    const int l7 = lane & 7, l8 = (lane >> 3) & 1, l16 = (lane >> 4) & 1;
    const int bm = blockIdx.y * 128;
    const int bn = blockIdx.x * 128;

    uint32_t aoffA[2], aoffB[4];
    #pragma unroll
    for (int mf = 0; mf < 2; mf++)
        aoffA[mf] = (uint32_t)(wm*32 + mf*16 + l7 + l8*8) * G_ROWB;
    #pragma unroll
    for (int nfp = 0; nfp < 4; nfp++)
        aoffB[nfp] = (uint32_t)(wn*64 + nfp*16 + l7 + l16*8) * G_ROWB;

    float acc[2][8][4];
    #pragma unroll
    for (int mf = 0; mf < 2; mf++)
        #pragma unroll
        for (int nf = 0; nf < 8; nf++)
            #pragma unroll
            for (int i = 0; i < 4; i++) acc[mf][nf][i] = 0.f;

    const int NIT = K / 32;

    auto load_tile = [&](int it, int st) {
        const int k0 = it * 32;
        #pragma unroll
        for (int j = 0; j < 2; j++) {
            int idx = j * 256 + tid;
            int r = idx >> 2, c = idx & 3;
            uint32_t d = sb + st * G_STAGE + (uint32_t)r * G_ROWB + c * 16;
            CP16(d + 0*G_ARR_B, Ahi + (size_t)(bm + r) * K + k0 + c*8);
            CP16(d + 1*G_ARR_B, Alo + (size_t)(bm + r) * K + k0 + c*8);
            CP16(d + 2*G_ARR_B, Bhi + (size_t)(bn + r) * K + k0 + c*8);
            CP16(d + 3*G_ARR_B, Blo + (size_t)(bn + r) * K + k0 + c*8);
        }
    };

    load_tile(0, 0);
    CP_COMMIT();

    for (int it = 0; it < NIT; it++) {
        const int st = it & 1;
        if (it + 1 < NIT) {
            load_tile(it + 1, st ^ 1);
            CP_COMMIT();
            CP_WAIT(1);
        } else {
            CP_WAIT(0);
        }
        __syncthreads();

        const uint32_t tAh = sb + st * G_STAGE;
        const uint32_t tAl = tAh + G_ARR_B;
        const uint32_t tBh = tAh + 2*G_ARR_B;
        const uint32_t tBl = tAh + 3*G_ARR_B;
        #pragma unroll
        for (int ks = 0; ks < 2; ks++) {
            const uint32_t ac = ks*32 + l16*16;
            const uint32_t bc = ks*32 + l8*16;
            uint32_t ah[2][4], al[2][4];
            #pragma unroll
            for (int mf = 0; mf < 2; mf++) {
                ldsm_x4(tAh + aoffA[mf] + ac, ah[mf][0], ah[mf][1], ah[mf][2], ah[mf][3]);
                ldsm_x4(tAl + aoffA[mf] + ac, al[mf][0], al[mf][1], al[mf][2], al[mf][3]);
            }
            #pragma unroll
            for (int nfp = 0; nfp < 4; nfp++) {
                uint32_t h0, h1, h2, h3, p0, p1, p2, p3;
                ldsm_x4(tBh + aoffB[nfp] + bc, h0, h1, h2, h3);
                ldsm_x4(tBl + aoffB[nfp] + bc, p0, p1, p2, p3);
                #pragma unroll
                for (int mf = 0; mf < 2; mf++) {
                    mma_bf16(acc[mf][2*nfp  ], ah[mf], h0, h1);
                    mma_bf16(acc[mf][2*nfp  ], ah[mf], p0, p1);
                    mma_bf16(acc[mf][2*nfp  ], al[mf], h0, h1);
                    mma_bf16(acc[mf][2*nfp+1], ah[mf], h2, h3);
                    mma_bf16(acc[mf][2*nfp+1], ah[mf], p2, p3);
                    mma_bf16(acc[mf][2*nfp+1], al[mf], h2, h3);
                }
            }
        }
        __syncthreads();
    }

    #pragma unroll
    for (int mf = 0; mf < 2; mf++) {
        #pragma unroll
        for (int nf = 0; nf < 8; nf++) {
            int row0 = bm + wm * 32 + mf * 16 + gi;
            int col  = bn + wn * 64 + nf * 8 + 2 * t;
            *reinterpret_cast<float2*>(C + (size_t)row0 * N + col) =
                make_float2(acc[mf][nf][0], acc[mf][nf][1]);
            *reinterpret_cast<float2*>(C + (size_t)(row0 + 8) * N + col) =
                make_float2(acc[mf][nf][2], acc[mf][nf][3]);
        }
    }
}

// ---------------- per-head LN on q/k + v split, bf16 split output ----------------
// units 0-15: q heads (LN, scale-fold); 16-19: k groups (LN); 20-23: v groups (split only)
__global__ __launch_bounds__(128) void qkln_kernel(const float* __restrict__ qs,
                                                   const float* __restrict__ qb,
                                                   const float* __restrict__ ks,
                                                   const float* __restrict__ kb) {
    int row  = blockIdx.x;
    int unit = blockIdx.y * 4 + (threadIdx.x >> 5);   // 0..23
    int lane = threadIdx.x & 31;
    int b = row / SEQ, n = row % SEQ;

    if (unit >= 20) {   // v: split only, store row-major [bg][n][64]
        int g = unit - 20;
        const float* p = g_kv + (size_t)row * KVDIM + 256 + g * 64;
        float v0 = p[lane], v1 = p[lane + 32];
        __nv_bfloat16 h0, l0, h1, l1;
        split_bf16(v0, h0, l0);
        split_bf16(v1, h1, l1);
        size_t base = ((size_t)(b * GROUPS + g) * SEQ + n) * 64;
        g_vh[base + lane] = h0;  g_vh[base + lane + 32] = h1;
        g_vl[base + lane] = l0;  g_vl[base + lane + 32] = l1;
        return;
    }

    const float *p, *sc, *bi;
    float postmul;
    if (unit < HEADS) {
        p = g_q + (size_t)row * INNER + unit * 64;
        sc = qs; bi = qb; postmul = 0.125f * LOG2E;
    } else {
        p = g_kv + (size_t)row * KVDIM + (unit - HEADS) * 64;
        sc = ks; bi = kb; postmul = 1.0f;
    }
    float v0 = p[lane], v1 = p[lane + 32];
    float s  = v0 + v1;
    float sq = v0*v0 + v1*v1;
    #pragma unroll
    for (int o = 16; o > 0; o >>= 1) {
        s  += __shfl_xor_sync(0xffffffffu, s,  o);
        sq += __shfl_xor_sync(0xffffffffu, sq, o);
    }
    float mean = s  * (1.f/64.f);
    float var  = sq * (1.f/64.f) - mean*mean;
    float rstd = rsqrtf(var + LN_EPS);
    float r0 = ((v0 - mean)*rstd*sc[lane]      + bi[lane]     ) * postmul;
    float r1 = ((v1 - mean)*rstd*sc[lane + 32] + bi[lane + 32]) * postmul;
    __nv_bfloat16 h0, l0, h1, l1;
    split_bf16(r0, h0, l0);
    split_bf16(r1, h1, l1);
    if (unit < HEADS) {
        size_t base = (size_t)row * INNER + unit * 64;
        g_qh[base + lane] = h0;  g_qh[base + lane + 32] = h1;
        g_ql[base + lane] = l0;  g_ql[base + lane + 32] = l1;
    } else {
        size_t base = ((size_t)(b * GROUPS + (unit - HEADS)) * SEQ + n) * 64;
        g_kh[base + lane] = h0;  g_kh[base + lane + 32] = h1;
        g_kl[base + lane] = l0;  g_kl[base + lane + 32] = l1;
    }
}

// ---------------- warp-MMA flash attention (32 q-rows/warp: K/V frags reused 2x) ----------------
// grid (SEQ/256, B*H), 256 threads = 8 warps, warp = 32 q rows x 64-wide kv tile.
// No online softmax (bounded logits: |S| <= 11.5 base-2 units, l in [0.7, 6e6], fp32-safe).
#define A_ROWB   144
#define A_ARR_B  (64*A_ROWB)
#define A_STAGE  (4*A_ARR_B)
#define A_SMEM   (2*A_STAGE)

__global__ __launch_bounds__(256) void attn_mma() {
    extern __shared__ char sma[];
    const uint32_t sb = smem_u32(sma);
    const int tid = threadIdx.x;
    const int warp = tid >> 5, lane = tid & 31;
    const int gi = lane >> 2, t = lane & 3;
    const int l7 = lane & 7, l8 = (lane >> 3) & 1, l16 = (lane >> 4) & 1;
    const int by = blockIdx.y;
    const int b = by / HEADS, h = by % HEADS;
    const int bg = b * GROUPS + h / HG;
    const int q0 = blockIdx.x * 256 + warp * 32;

    // K fragment (non-trans): rows keyed on l16, k-columns keyed on l8 (verified R5/R11)
    uint32_t aoffK[4];
    #pragma unroll
    for (int nfp = 0; nfp < 4; nfp++)
        aoffK[nfp] = (uint32_t)(nfp*16 + l7 + l16*8) * A_ROWB;
    // V fragment (trans) addressing (verified R11)
    const uint32_t vrow = (uint32_t)(lane & 15);
    const uint32_t vcolb = (uint32_t)l16 * 16;

    // load Q fragments (hi/lo) for both 16-row subtiles, keep in regs
    uint32_t qh[2][4][4], ql[2][4][4];
    {
        const uint32_t* ph = reinterpret_cast<const uint32_t*>(g_qh);
        const uint32_t* pl = reinterpret_cast<const uint32_t*>(g_ql);
        #pragma unroll
        for (int mf = 0; mf < 2; mf++) {
            #pragma unroll
            for (int kf = 0; kf < 4; kf++) {
                int col = kf * 16 + 2 * t;
                size_t i0 = ((size_t)(b*SEQ + q0 + mf*16 + gi    ) * INNER + h*64 + col) >> 1;
                size_t i1 = ((size_t)(b*SEQ + q0 + mf*16 + gi + 8) * INNER + h*64 + col) >> 1;
                qh[mf][kf][0] = ph[i0]; qh[mf][kf][1] = ph[i1];
                qh[mf][kf][2] = ph[i0 + 4]; qh[mf][kf][3] = ph[i1 + 4];
                ql[mf][kf][0] = pl[i0]; ql[mf][kf][1] = pl[i1];
                ql[mf][kf][2] = pl[i0 + 4]; ql[mf][kf][3] = pl[i1 + 4];
            }
        }
    }

    float o[2][8][4];
    #pragma unroll
    for (int mf = 0; mf < 2; mf++)
        #pragma unroll
        for (int nd = 0; nd < 8; nd++)
            #pragma unroll
            for (int i = 0; i < 4; i++) o[mf][nd][i] = 0.f;
    float lacc[2][2];
    lacc[0][0] = lacc[0][1] = lacc[1][0] = lacc[1][1] = 0.f;

    const __nv_bfloat16* kh_b = g_kh + (size_t)bg * SEQ * 64;
    const __nv_bfloat16* kl_b = g_kl + (size_t)bg * SEQ * 64;
    const __nv_bfloat16* vh_b = g_vh + (size_t)bg * SEQ * 64;
    const __nv_bfloat16* vl_b = g_vl + (size_t)bg * SEQ * 64;

    auto load_tile = [&](int t0, int st) {
        #pragma unroll
        for (int j = 0; j < 2; j++) {
            int idx = j * 256 + tid;
            int r = idx >> 3, c = idx & 7;
            size_t roff = (size_t)(t0 + r) * 64 + c * 8;
            uint32_t d = sb + st * A_STAGE + (uint32_t)r * A_ROWB + c * 16;
            CP16(d + 0*A_ARR_B, kh_b + roff);
            CP16(d + 1*A_ARR_B, kl_b + roff);
            CP16(d + 2*A_ARR_B, vh_b + roff);
            CP16(d + 3*A_ARR_B, vl_b + roff);
        }
    };

    load_tile(0, 0);
    CP_COMMIT();

    const int NIT = SEQ / 64;
    for (int it = 0; it < NIT; it++) {
        const int st = it & 1;
        if (it + 1 < NIT) {
            load_tile((it + 1) * 64, st ^ 1);
            CP_COMMIT();
            CP_WAIT(1);
        } else {
            CP_WAIT(0);
        }
        __syncthreads();

        const uint32_t tKh = sb + st * A_STAGE;
        const uint32_t tKl = tKh + A_ARR_B;
        const uint32_t tVh = tKh + 2*A_ARR_B;
        const uint32_t tVl = tKh + 3*A_ARR_B;

        // S = Q K^T (split 3-product), both q-subtiles sharing each K fragment
        float s[2][8][4];
        #pragma unroll
        for (int mf = 0; mf < 2; mf++)
            #pragma unroll
            for (int nf = 0; nf < 8; nf++)
                #pragma unroll
                for (int i = 0; i < 4; i++) s[mf][nf][i] = 0.f;
        #pragma unroll
        for (int kf = 0; kf < 4; kf++) {
            const uint32_t bc = kf*32 + l8*16;
            #pragma unroll
            for (int nfp = 0; nfp < 4; nfp++) {
                uint32_t h0, h1, h2, h3, p0, p1, p2, p3;
                ldsm_x4(tKh + aoffK[nfp] + bc, h0, h1, h2, h3);
                ldsm_x4(tKl + aoffK[nfp] + bc, p0, p1, p2, p3);
                #pragma unroll
                for (int mf = 0; mf < 2; mf++) {
                    mma_bf16(s[mf][2*nfp  ], qh[mf][kf], h0, h1);
                    mma_bf16(s[mf][2*nfp  ], qh[mf][kf], p0, p1);
                    mma_bf16(s[mf][2*nfp  ], ql[mf][kf], h0, h1);
                    mma_bf16(s[mf][2*nfp+1], qh[mf][kf], h2, h3);
                    mma_bf16(s[mf][2*nfp+1], qh[mf][kf], p2, p3);
                    mma_bf16(s[mf][2*nfp+1], ql[mf][kf], h2, h3);
                }
            }
        }

        // p = exp2(S); per-thread partial row-sums; pack to A-frags hi/lo
        uint32_t pah[2][4][4], pal[2][4][4];
        #pragma unroll
        for (int mf = 0; mf < 2; mf++) {
            #pragma unroll
            for (int nf = 0; nf < 8; nf++) {
                s[mf][nf][0] = fexp2(s[mf][nf][0]);
                s[mf][nf][1] = fexp2(s[mf][nf][1]);
                s[mf][nf][2] = fexp2(s[mf][nf][2]);
                s[mf][nf][3] = fexp2(s[mf][nf][3]);
                lacc[mf][0] += s[mf][nf][0] + s[mf][nf][1];
                lacc[mf][1] += s[mf][nf][2] + s[mf][nf][3];
            }
            #pragma unroll
            for (int kf = 0; kf < 4; kf++) {
                split_pack2(s[mf][2*kf    ][0], s[mf][2*kf    ][1], pah[mf][kf][0], pal[mf][kf][0]);
                split_pack2(s[mf][2*kf    ][2], s[mf][2*kf    ][3], pah[mf][kf][1], pal[mf][kf][1]);
                split_pack2(s[mf][2*kf + 1][0], s[mf][2*kf + 1][1], pah[mf][kf][2], pal[mf][kf][2]);
                split_pack2(s[mf][2*kf + 1][2], s[mf][2*kf + 1][3], pah[mf][kf][3], pal[mf][kf][3]);
            }
        }

        // O += P @ V (3-product; V row-major, ldmatrix.trans), V frags shared across mf
        #pragma unroll
        for (int kf = 0; kf < 4; kf++) {
            const uint32_t vro = (uint32_t)(kf*16 + vrow) * A_ROWB + vcolb;
            #pragma unroll
            for (int ndp = 0; ndp < 4; ndp++) {
                uint32_t h0, h1, h2, h3, p0, p1, p2, p3;
                ldsm_x4_t(tVh + vro + ndp*32, h0, h1, h2, h3);
                ldsm_x4_t(tVl + vro + ndp*32, p0, p1, p2, p3);
                #pragma unroll
                for (int mf = 0; mf < 2; mf++) {
                    mma_bf16(o[mf][2*ndp  ], pah[mf][kf], h0, h1);
                    mma_bf16(o[mf][2*ndp  ], pah[mf][kf], p0, p1);
                    mma_bf16(o[mf][2*ndp  ], pal[mf][kf], h0, h1);
                    mma_bf16(o[mf][2*ndp+1], pah[mf][kf], h2, h3);
                    mma_bf16(o[mf][2*ndp+1], pah[mf][kf], p2, p3);
                    mma_bf16(o[mf][2*ndp+1], pal[mf][kf], h2, h3);
                }
            }
        }
        __syncthreads();
    }

    // final reduction of row sums across the 4 lanes of each row
    #pragma unroll
    for (int mf = 0; mf < 2; mf++) {
        lacc[mf][0] += __shfl_xor_sync(0xffffffffu, lacc[mf][0], 1);
        lacc[mf][0] += __shfl_xor_sync(0xffffffffu, lacc[mf][0], 2);
        lacc[mf][1] += __shfl_xor_sync(0xffffffffu, lacc[mf][1], 1);
        lacc[mf][1] += __shfl_xor_sync(0xffffffffu, lacc[mf][1], 2);
    }

    // epilogue: normalize, split, store bf16 hi/lo
    #pragma unroll
    for (int mf = 0; mf < 2; mf++) {
        float inv0 = 1.f / lacc[mf][0], inv1 = 1.f / lacc[mf][1];
        #pragma unroll
        for (int nd = 0; nd < 8; nd++) {
            float v0 = o[mf][nd][0] * inv0, v1 = o[mf][nd][1] * inv0;
            float v2 = o[mf][nd][2] * inv1, v3 = o[mf][nd][3] * inv1;
            size_t i0 = (size_t)(b*SEQ + q0 + mf*16 + gi    ) * INNER + h*64 + nd*8 + 2*t;
            size_t i1 = (size_t)(b*SEQ + q0 + mf*16 + gi + 8) * INNER + h*64 + nd*8 + 2*t;
            uint32_t hw, lw;
            split_pack2(v0, v1, hw, lw);
            *reinterpret_cast<uint32_t*>(g_oh + i0) = hw;
            *reinterpret_cast<uint32_t*>(g_ol + i0) = lw;
            split_pack2(v2, v3, hw, lw);
            *reinterpret_cast<uint32_t*>(g_oh + i1) = hw;
            *reinterpret_cast<uint32_t*>(g_ol + i1) = lw;
        }
    }
}

extern "C" void kernel_launch(void* const* d_in, const int* in_sizes, int n_in,
                              void* d_out, int out_size) {
    const float* x    = (const float*)d_in[0];
    const float* lns  = (const float*)d_in[1];
    const float* lnb  = (const float*)d_in[2];
    const float* Wq   = (const float*)d_in[3];
    const float* Wkv  = (const float*)d_in[4];
    const float* qns  = (const float*)d_in[5];
    const float* qnb  = (const float*)d_in[6];
    const float* kns  = (const float*)d_in[7];
    const float* knb  = (const float*)d_in[8];
    const float* Wout = (const float*)d_in[9];
    float* out = (float*)d_out;

    void *pxh, *pxl, *pq, *pkv;
    void *poh, *pol, *pwqh, *pwql, *pwkh, *pwkl, *pwoh, *pwol;
    cudaGetSymbolAddress(&pxh, g_xn_hi);  cudaGetSymbolAddress(&pxl, g_xn_lo);
    cudaGetSymbolAddress(&pq,  g_q);      cudaGetSymbolAddress(&pkv, g_kv);
    cudaGetSymbolAddress(&poh, g_oh);     cudaGetSymbolAddress(&pol, g_ol);
    cudaGetSymbolAddress(&pwqh, g_wq_hi); cudaGetSymbolAddress(&pwql, g_wq_lo);
    cudaGetSymbolAddress(&pwkh, g_wkv_hi);cudaGetSymbolAddress(&pwkl, g_wkv_lo);
    cudaGetSymbolAddress(&pwoh, g_wo_hi); cudaGetSymbolAddress(&pwol, g_wo_lo);

    cudaFuncSetAttribute(gemm_mma, cudaFuncAttributeMaxDynamicSharedMemorySize, G_SMEM);
    cudaFuncSetAttribute(attn_mma, cudaFuncAttributeMaxDynamicSharedMemorySize, A_SMEM);

    ln_kernel<<<ROWS, 256>>>(x, lns, lnb);
    wconv_kernel<<<dim3(INNER/32, DIM/32), 256>>>(Wq,   (__nv_bfloat16*)pwqh, (__nv_bfloat16*)pwql, DIM, INNER);
    wconv_kernel<<<dim3(KVDIM/32, DIM/32), 256>>>(Wkv,  (__nv_bfloat16*)pwkh, (__nv_bfloat16*)pwkl, DIM, KVDIM);
    wconv_kernel<<<dim3(DIM/32, INNER/32), 256>>>(Wout, (__nv_bfloat16*)pwoh, (__nv_bfloat16*)pwol, INNER, DIM);

    gemm_mma<<<dim3(INNER/128, ROWS/128), 256, G_SMEM>>>(
        (const __nv_bfloat16*)pxh, (const __nv_bfloat16*)pxl,
        (const __nv_bfloat16*)pwqh, (const __nv_bfloat16*)pwql,
        (float*)pq, INNER, DIM);
    gemm_mma<<<dim3(KVDIM/128, ROWS/128), 256, G_SMEM>>>(
        (const __nv_bfloat16*)pxh, (const __nv_bfloat16*)pxl,
        (const __nv_bfloat16*)pwkh, (const __nv_bfloat16*)pwkl,
        (float*)pkv, KVDIM, DIM);
    qkln_kernel<<<dim3(ROWS, 6), 128>>>(qns, qnb, kns, knb);
    attn_mma<<<dim3(SEQ/256, BATCH*HEADS), 256, A_SMEM>>>();
    gemm_mma<<<dim3(DIM/128, ROWS/128), 256, G_SMEM>>>(
        (const __nv_bfloat16*)poh, (const __nv_bfloat16*)pol,
        (const __nv_bfloat16*)pwoh, (const __nv_bfloat16*)pwol,
        out, DIM, INNER);
}

// round 14
// speedup vs baseline: 1.5042x; 1.5042x over previous
#include <cuda_runtime.h>
#include <cuda_fp16.h>
#include <cstdint>

#define DIM    1024
#define HEADS  16
#define GROUPS 4
#define HG     (HEADS/GROUPS)
#define DHEAD  64
#define INNER  1024
#define KVDIM  512
#define BATCH  4
#define SEQ    2048
#define ROWS   (BATCH*SEQ)
#define LN_EPS 1e-6f
#define LOG2E  1.44269504088896f

// ---------------- scratch (__device__ globals, allocation-free) ----------------
__device__ __align__(16) __half g_xn_hi[ROWS*DIM];
__device__ __align__(16) __half g_xn_lo[ROWS*DIM];
__device__ __align__(16) float  g_q [ROWS*INNER];
__device__ __align__(16) float  g_kv[ROWS*KVDIM];
__device__ __align__(16) __half g_qh[ROWS*INNER];      // q hi
__device__ __align__(16) __half g_ql[ROWS*INNER];      // q lo
__device__ __align__(16) __half g_k [BATCH*GROUPS*SEQ*DHEAD];  // k single fp16
__device__ __align__(16) __half g_vh[BATCH*GROUPS*SEQ*DHEAD];  // v hi, row-major [bg][n][d]
__device__ __align__(16) __half g_vl[BATCH*GROUPS*SEQ*DHEAD];  // v lo
__device__ __align__(16) __half g_oh[ROWS*INNER];
__device__ __align__(16) __half g_ol[ROWS*INNER];
__device__ __align__(16) __half g_wq [INNER*DIM];      // single fp16 [N,K]
__device__ __align__(16) __half g_wkv[KVDIM*DIM];
__device__ __align__(16) __half g_wo [DIM*INNER];

// ---------------- helpers ----------------
__device__ __forceinline__ uint32_t smem_u32(const void* p) {
    uint32_t a;
    asm("{ .reg .u64 t; cvta.to.shared.u64 t, %1; cvt.u32.u64 %0, t; }" : "=r"(a) : "l"(p));
    return a;
}
__device__ __forceinline__ void mma_f16(float c[4], const uint32_t a[4],
                                        uint32_t b0, uint32_t b1) {
    asm volatile(
        "mma.sync.aligned.m16n8k16.row.col.f32.f16.f16.f32 "
        "{%0,%1,%2,%3}, {%4,%5,%6,%7}, {%8,%9}, {%0,%1,%2,%3};"
        : "+f"(c[0]), "+f"(c[1]), "+f"(c[2]), "+f"(c[3])
        : "r"(a[0]), "r"(a[1]), "r"(a[2]), "r"(a[3]), "r"(b0), "r"(b1));
}
__device__ __forceinline__ void ldsm_x4(uint32_t addr, uint32_t& r0, uint32_t& r1,
                                        uint32_t& r2, uint32_t& r3) {
    asm volatile("ldmatrix.sync.aligned.m8n8.x4.shared.b16 {%0,%1,%2,%3}, [%4];"
        : "=r"(r0), "=r"(r1), "=r"(r2), "=r"(r3) : "r"(addr));
}
__device__ __forceinline__ void ldsm_x4_t(uint32_t addr, uint32_t& r0, uint32_t& r1,
                                          uint32_t& r2, uint32_t& r3) {
    asm volatile("ldmatrix.sync.aligned.m8n8.x4.trans.shared.b16 {%0,%1,%2,%3}, [%4];"
        : "=r"(r0), "=r"(r1), "=r"(r2), "=r"(r3) : "r"(addr));
}
#define CP16(dst, src) \
    asm volatile("cp.async.cg.shared.global [%0], [%1], 16;" :: "r"(dst), "l"(src))
#define CP_COMMIT() asm volatile("cp.async.commit_group;" ::: "memory")
#define CP_WAIT(n)  asm volatile("cp.async.wait_group %0;" :: "n"(n) : "memory")

__device__ __forceinline__ float fexp2(float x) {
    float r;
    asm("ex2.approx.f32 %0, %1;" : "=f"(r) : "f"(x));
    return r;
}
__device__ __forceinline__ void split_h(float v, __half& h, __half& l) {
    h = __float2half_rn(v);
    l = __float2half_rn(v - __half2float(h));
}
__device__ __forceinline__ uint32_t packh2(float a, float b) {
    __half2 p = __floats2half2_rn(a, b);
    return *reinterpret_cast<uint32_t*>(&p);
}
__device__ __forceinline__ void split_packh2(float v0, float v1, uint32_t& hw, uint32_t& lw) {
    __half h0, l0, h1, l1;
    split_h(v0, h0, l0);
    split_h(v1, h1, l1);
    __half2 ph(h0, h1), pl(l0, l1);
    hw = *reinterpret_cast<uint32_t*>(&ph);
    lw = *reinterpret_cast<uint32_t*>(&pl);
}

// ---------------- input layernorm, emits fp16 hi/lo split ----------------
__global__ __launch_bounds__(256) void ln_kernel(const float* __restrict__ x,
                                                 const float* __restrict__ sc,
                                                 const float* __restrict__ bi) {
    int row = blockIdx.x;
    int t = threadIdx.x;
    const float4 a = reinterpret_cast<const float4*>(x)[row*(DIM/4) + t];
    float s  = a.x + a.y + a.z + a.w;
    float sq = a.x*a.x + a.y*a.y + a.z*a.z + a.w*a.w;
    #pragma unroll
    for (int o = 16; o > 0; o >>= 1) {
        s  += __shfl_xor_sync(0xffffffffu, s,  o);
        sq += __shfl_xor_sync(0xffffffffu, sq, o);
    }
    __shared__ float ws[8], wq[8];
    if ((t & 31) == 0) { ws[t >> 5] = s; wq[t >> 5] = sq; }
    __syncthreads();
    s = 0.f; sq = 0.f;
    #pragma unroll
    for (int i = 0; i < 8; i++) { s += ws[i]; sq += wq[i]; }
    float mean = s  * (1.f/DIM);
    float var  = sq * (1.f/DIM) - mean*mean;
    float rstd = rsqrtf(var + LN_EPS);
    float4 s4 = reinterpret_cast<const float4*>(sc)[t];
    float4 b4 = reinterpret_cast<const float4*>(bi)[t];
    float v[4];
    v[0] = (a.x - mean)*rstd*s4.x + b4.x;
    v[1] = (a.y - mean)*rstd*s4.y + b4.y;
    v[2] = (a.z - mean)*rstd*s4.z + b4.z;
    v[3] = (a.w - mean)*rstd*s4.w + b4.w;
    __half hi[4], lo[4];
    #pragma unroll
    for (int i = 0; i < 4; i++) split_h(v[i], hi[i], lo[i]);
    size_t base = (size_t)row * DIM + t * 4;
    *reinterpret_cast<__half2*>(g_xn_hi + base)     = __half2(hi[0], hi[1]);
    *reinterpret_cast<__half2*>(g_xn_hi + base + 2) = __half2(hi[2], hi[3]);
    *reinterpret_cast<__half2*>(g_xn_lo + base)     = __half2(lo[0], lo[1]);
    *reinterpret_cast<__half2*>(g_xn_lo + base + 2) = __half2(lo[2], lo[3]);
}

// ---------------- weight transpose: W[K,N] fp32 -> T[N,K] single fp16 ----------------
__global__ __launch_bounds__(256) void wconv_kernel(const float* __restrict__ W,
                                                    __half* __restrict__ T,
                                                    int K, int N) {
    __shared__ float tile[32][33];
    int kb = blockIdx.y * 32, nb = blockIdx.x * 32;
    int tx = threadIdx.x & 31, ty = threadIdx.x >> 5;  // 32 x 8
    #pragma unroll
    for (int i = ty; i < 32; i += 8)
        tile[i][tx] = W[(size_t)(kb + i) * N + nb + tx];
    __syncthreads();
    #pragma unroll
    for (int i = ty; i < 32; i += 8)
        T[(size_t)(nb + i) * K + kb + tx] = __float2half_rn(tile[tx][i]);
}

// ---------------- warp-MMA GEMM: A split fp16 hi/lo, W single fp16, 2 products ----------------
#define G_ROWB   80
#define G_ARR_B  (128*G_ROWB)
#define G_STAGE  (3*G_ARR_B)     // Ah, Al, W
#define G_SMEM   (2*G_STAGE)

__global__ __launch_bounds__(256, 2) void gemm_mma(const __half* __restrict__ Ahi,
                                                   const __half* __restrict__ Alo,
                                                   const __half* __restrict__ W,
                                                   float* __restrict__ C, int N, int K) {
    extern __shared__ char smg[];
    const uint32_t sb = smem_u32(smg);
    const int tid  = threadIdx.x;
    const int warp = tid >> 5, lane = tid & 31;
    const int wm = warp & 3, wn = warp >> 2;
    const int gi = lane >> 2, t = lane & 3;
    const int l7 = lane & 7, l8 = (lane >> 3) & 1, l16 = (lane >> 4) & 1;
    const int bm = blockIdx.y * 128;
    const int bn = blockIdx.x * 128;

    uint32_t aoffA[2], aoffB[4];
    #pragma unroll
    for (int mf = 0; mf < 2; mf++)
        aoffA[mf] = (uint32_t)(wm*32 + mf*16 + l7 + l8*8) * G_ROWB;
    #pragma unroll
    for (int nfp = 0; nfp < 4; nfp++)
        aoffB[nfp] = (uint32_t)(wn*64 + nfp*16 + l7 + l16*8) * G_ROWB;

    float acc[2][8][4];
    #pragma unroll
    for (int mf = 0; mf < 2; mf++)
        #pragma unroll
        for (int nf = 0; nf < 8; nf++)
            #pragma unroll
            for (int i = 0; i < 4; i++) acc[mf][nf][i] = 0.f;

    const int NIT = K / 32;

    auto load_tile = [&](int it, int st) {
        const int k0 = it * 32;
        #pragma unroll
        for (int j = 0; j < 2; j++) {
            int idx = j * 256 + tid;
            int r = idx >> 2, c = idx & 3;
            uint32_t d = sb + st * G_STAGE + (uint32_t)r * G_ROWB + c * 16;
            CP16(d + 0*G_ARR_B, Ahi + (size_t)(bm + r) * K + k0 + c*8);
            CP16(d + 1*G_ARR_B, Alo + (size_t)(bm + r) * K + k0 + c*8);
            CP16(d + 2*G_ARR_B, W   + (size_t)(bn + r) * K + k0 + c*8);
        }
    };

    load_tile(0, 0);
    CP_COMMIT();

    for (int it = 0; it < NIT; it++) {
        const int st = it & 1;
        if (it + 1 < NIT) {
            load_tile(it + 1, st ^ 1);
            CP_COMMIT();
            CP_WAIT(1);
        } else {
            CP_WAIT(0);
        }
        __syncthreads();

        const uint32_t tAh = sb + st * G_STAGE;
        const uint32_t tAl = tAh + G_ARR_B;
        const uint32_t tW  = tAh + 2*G_ARR_B;
        #pragma unroll
        for (int ks = 0; ks < 2; ks++) {
            const uint32_t ac = ks*32 + l16*16;
            const uint32_t bc = ks*32 + l8*16;
            uint32_t ah[2][4], al[2][4];
            #pragma unroll
            for (int mf = 0; mf < 2; mf++) {
                ldsm_x4(tAh + aoffA[mf] + ac, ah[mf][0], ah[mf][1], ah[mf][2], ah[mf][3]);
                ldsm_x4(tAl + aoffA[mf] + ac, al[mf][0], al[mf][1], al[mf][2], al[mf][3]);
            }
            #pragma unroll
            for (int nfp = 0; nfp < 4; nfp++) {
                uint32_t w0, w1, w2, w3;
                ldsm_x4(tW + aoffB[nfp] + bc, w0, w1, w2, w3);
                #pragma unroll
                for (int mf = 0; mf < 2; mf++) {
                    mma_f16(acc[mf][2*nfp  ], ah[mf], w0, w1);
                    mma_f16(acc[mf][2*nfp  ], al[mf], w0, w1);
                    mma_f16(acc[mf][2*nfp+1], ah[mf], w2, w3);
                    mma_f16(acc[mf][2*nfp+1], al[mf], w2, w3);
                }
            }
        }
        __syncthreads();
    }

    #pragma unroll
    for (int mf = 0; mf < 2; mf++) {
        #pragma unroll
        for (int nf = 0; nf < 8; nf++) {
            int row0 = bm + wm * 32 + mf * 16 + gi;
            int col  = bn + wn * 64 + nf * 8 + 2 * t;
            *reinterpret_cast<float2*>(C + (size_t)row0 * N + col) =
                make_float2(acc[mf][nf][0], acc[mf][nf][1]);
            *reinterpret_cast<float2*>(C + (size_t)(row0 + 8) * N + col) =
                make_float2(acc[mf][nf][2], acc[mf][nf][3]);
        }
    }
}

// ---------------- per-head LN on q/k + v split, fp16 outputs ----------------
// units 0-15: q heads (LN, hi/lo); 16-19: k groups (LN, single); 20-23: v groups (hi/lo)
__global__ __launch_bounds__(128) void qkln_kernel(const float* __restrict__ qs,
                                                   const float* __restrict__ qb,
                                                   const float* __restrict__ ks,
                                                   const float* __restrict__ kb) {
    int row  = blockIdx.x;
    int unit = blockIdx.y * 4 + (threadIdx.x >> 5);   // 0..23
    int lane = threadIdx.x & 31;
    int b = row / SEQ, n = row % SEQ;

    if (unit >= 20) {   // v: split only, store row-major [bg][n][64]
        int g = unit - 20;
        const float* p = g_kv + (size_t)row * KVDIM + 256 + g * 64;
        float v0 = p[lane], v1 = p[lane + 32];
        __half h0, l0, h1, l1;
        split_h(v0, h0, l0);
        split_h(v1, h1, l1);
        size_t base = ((size_t)(b * GROUPS + g) * SEQ + n) * 64;
        g_vh[base + lane] = h0;  g_vh[base + lane + 32] = h1;
        g_vl[base + lane] = l0;  g_vl[base + lane + 32] = l1;
        return;
    }

    const float *p, *sc, *bi;
    float postmul;
    if (unit < HEADS) {
        p = g_q + (size_t)row * INNER + unit * 64;
        sc = qs; bi = qb; postmul = 0.125f * LOG2E;
    } else {
        p = g_kv + (size_t)row * KVDIM + (unit - HEADS) * 64;
        sc = ks; bi = kb; postmul = 1.0f;
    }
    float v0 = p[lane], v1 = p[lane + 32];
    float s  = v0 + v1;
    float sq = v0*v0 + v1*v1;
    #pragma unroll
    for (int o = 16; o > 0; o >>= 1) {
        s  += __shfl_xor_sync(0xffffffffu, s,  o);
        sq += __shfl_xor_sync(0xffffffffu, sq, o);
    }
    float mean = s  * (1.f/64.f);
    float var  = sq * (1.f/64.f) - mean*mean;
    float rstd = rsqrtf(var + LN_EPS);
    float r0 = ((v0 - mean)*rstd*sc[lane]      + bi[lane]     ) * postmul;
    float r1 = ((v1 - mean)*rstd*sc[lane + 32] + bi[lane + 32]) * postmul;
    if (unit < HEADS) {
        __half h0, l0, h1, l1;
        split_h(r0, h0, l0);
        split_h(r1, h1, l1);
        size_t base = (size_t)row * INNER + unit * 64;
        g_qh[base + lane] = h0;  g_qh[base + lane + 32] = h1;
        g_ql[base + lane] = l0;  g_ql[base + lane + 32] = l1;
    } else {
        size_t base = ((size_t)(b * GROUPS + (unit - HEADS)) * SEQ + n) * 64;
        g_k[base + lane]      = __float2half_rn(r0);
        g_k[base + lane + 32] = __float2half_rn(r1);
    }
}

// ---------------- warp-MMA flash attention (fp16, 2-product QK & PV, no online softmax) ----------------
// grid (SEQ/128, B*H), 256 threads = 8 warps, warp = 16 q rows x 64-wide kv tile.
// Bounded logits: |S| <= 11.5 base-2 units, l in [0.7, 6e6], fp32-safe without max tracking.
#define A_ROWB   144
#define A_ARR_B  (64*A_ROWB)
#define A_STAGE  (3*A_ARR_B)    // K, Vh, Vl
#define A_SMEM   (2*A_STAGE)

__global__ __launch_bounds__(256) void attn_mma() {
    extern __shared__ char sma[];
    const uint32_t sb = smem_u32(sma);
    const int tid = threadIdx.x;
    const int warp = tid >> 5, lane = tid & 31;
    const int gi = lane >> 2, t = lane & 3;
    const int l7 = lane & 7, l8 = (lane >> 3) & 1, l16 = (lane >> 4) & 1;
    const int by = blockIdx.y;
    const int b = by / HEADS, h = by % HEADS;
    const int bg = b * GROUPS + h / HG;
    const int q0 = blockIdx.x * 128 + warp * 16;

    // K fragment (non-trans): rows keyed on l16, k-columns keyed on l8 (verified R5/R11)
    uint32_t aoffK[4];
    #pragma unroll
    for (int nfp = 0; nfp < 4; nfp++)
        aoffK[nfp] = (uint32_t)(nfp*16 + l7 + l16*8) * A_ROWB;
    // V fragment (trans) addressing (verified R11)
    const uint32_t vrow = (uint32_t)(lane & 15);
    const uint32_t vcolb = (uint32_t)l16 * 16;

    // load Q fragments (hi/lo) once, keep in regs
    uint32_t qh[4][4], ql[4][4];
    {
        const uint32_t* ph = reinterpret_cast<const uint32_t*>(g_qh);
        const uint32_t* pl = reinterpret_cast<const uint32_t*>(g_ql);
        #pragma unroll
        for (int kf = 0; kf < 4; kf++) {
            int col = kf * 16 + 2 * t;
            size_t i0 = ((size_t)(b*SEQ + q0 + gi    ) * INNER + h*64 + col) >> 1;
            size_t i1 = ((size_t)(b*SEQ + q0 + gi + 8) * INNER + h*64 + col) >> 1;
            qh[kf][0] = ph[i0]; qh[kf][1] = ph[i1]; qh[kf][2] = ph[i0 + 4]; qh[kf][3] = ph[i1 + 4];
            ql[kf][0] = pl[i0]; ql[kf][1] = pl[i1]; ql[kf][2] = pl[i0 + 4]; ql[kf][3] = pl[i1 + 4];
        }
    }

    float o[8][4];
    #pragma unroll
    for (int nd = 0; nd < 8; nd++)
        #pragma unroll
        for (int i = 0; i < 4; i++) o[nd][i] = 0.f;
    float l0 = 0.f, l1 = 0.f;

    const __half* k_b  = g_k  + (size_t)bg * SEQ * 64;
    const __half* vh_b = g_vh + (size_t)bg * SEQ * 64;
    const __half* vl_b = g_vl + (size_t)bg * SEQ * 64;

    auto load_tile = [&](int t0, int st) {
        #pragma unroll
        for (int j = 0; j < 2; j++) {
            int idx = j * 256 + tid;
            int r = idx >> 3, c = idx & 7;
            size_t roff = (size_t)(t0 + r) * 64 + c * 8;
            uint32_t d = sb + st * A_STAGE + (uint32_t)r * A_ROWB + c * 16;
            CP16(d + 0*A_ARR_B, k_b  + roff);
            CP16(d + 1*A_ARR_B, vh_b + roff);
            CP16(d + 2*A_ARR_B, vl_b + roff);
        }
    };

    load_tile(0, 0);
    CP_COMMIT();

    const int NIT = SEQ / 64;
    for (int it = 0; it < NIT; it++) {
        const int st = it & 1;
        if (it + 1 < NIT) {
            load_tile((it + 1) * 64, st ^ 1);
            CP_COMMIT();
            CP_WAIT(1);
        } else {
            CP_WAIT(0);
        }
        __syncthreads();

        const uint32_t tK  = sb + st * A_STAGE;
        const uint32_t tVh = tK + A_ARR_B;
        const uint32_t tVl = tK + 2*A_ARR_B;

        // S = Q K^T (q split 2-product, k single)
        float s[8][4];
        #pragma unroll
        for (int nf = 0; nf < 8; nf++)
            #pragma unroll
            for (int i = 0; i < 4; i++) s[nf][i] = 0.f;
        #pragma unroll
        for (int kf = 0; kf < 4; kf++) {
            const uint32_t bc = kf*32 + l8*16;
            #pragma unroll
            for (int nfp = 0; nfp < 4; nfp++) {
                uint32_t k0, k1, k2, k3;
                ldsm_x4(tK + aoffK[nfp] + bc, k0, k1, k2, k3);
                mma_f16(s[2*nfp  ], qh[kf], k0, k1);
                mma_f16(s[2*nfp  ], ql[kf], k0, k1);
                mma_f16(s[2*nfp+1], qh[kf], k2, k3);
                mma_f16(s[2*nfp+1], ql[kf], k2, k3);
            }
        }

        // p = exp2(S); per-thread partial row-sums; pack P single fp16
        uint32_t pa[4][4];
        #pragma unroll
        for (int nf = 0; nf < 8; nf++) {
            s[nf][0] = fexp2(s[nf][0]);
            s[nf][1] = fexp2(s[nf][1]);
            s[nf][2] = fexp2(s[nf][2]);
            s[nf][3] = fexp2(s[nf][3]);
            l0 += s[nf][0] + s[nf][1];
            l1 += s[nf][2] + s[nf][3];
        }
        #pragma unroll
        for (int kf = 0; kf < 4; kf++) {
            pa[kf][0] = packh2(s[2*kf    ][0], s[2*kf    ][1]);
            pa[kf][1] = packh2(s[2*kf    ][2], s[2*kf    ][3]);
            pa[kf][2] = packh2(s[2*kf + 1][0], s[2*kf + 1][1]);
            pa[kf][3] = packh2(s[2*kf + 1][2], s[2*kf + 1][3]);
        }

        // O += P @ V (p single, v split 2-product; V row-major, ldmatrix.trans)
        #pragma unroll
        for (int kf = 0; kf < 4; kf++) {
            const uint32_t vro = (uint32_t)(kf*16 + vrow) * A_ROWB + vcolb;
            #pragma unroll
            for (int ndp = 0; ndp < 4; ndp++) {
                uint32_t h0, h1, h2, h3, p0, p1, p2, p3;
                ldsm_x4_t(tVh + vro + ndp*32, h0, h1, h2, h3);
                ldsm_x4_t(tVl + vro + ndp*32, p0, p1, p2, p3);
                mma_f16(o[2*ndp  ], pa[kf], h0, h1);
                mma_f16(o[2*ndp  ], pa[kf], p0, p1);
                mma_f16(o[2*ndp+1], pa[kf], h2, h3);
                mma_f16(o[2*ndp+1], pa[kf], p2, p3);
            }
        }
        __syncthreads();
    }

    // single final reduction of row sums across the 4 lanes of each row
    l0 += __shfl_xor_sync(0xffffffffu, l0, 1);
    l0 += __shfl_xor_sync(0xffffffffu, l0, 2);
    l1 += __shfl_xor_sync(0xffffffffu, l1, 1);
    l1 += __shfl_xor_sync(0xffffffffu, l1, 2);

    // epilogue: normalize, split fp16 hi/lo
    float inv0 = 1.f / l0, inv1 = 1.f / l1;
    #pragma unroll
    for (int nd = 0; nd < 8; nd++) {
        float v0 = o[nd][0] * inv0, v1 = o[nd][1] * inv0;
        float v2 = o[nd][2] * inv1, v3 = o[nd][3] * inv1;
        size_t i0 = (size_t)(b*SEQ + q0 + gi    ) * INNER + h*64 + nd*8 + 2*t;
        size_t i1 = (size_t)(b*SEQ + q0 + gi + 8) * INNER + h*64 + nd*8 + 2*t;
        uint32_t hw, lw;
        split_packh2(v0, v1, hw, lw);
        *reinterpret_cast<uint32_t*>(g_oh + i0) = hw;
        *reinterpret_cast<uint32_t*>(g_ol + i0) = lw;
        split_packh2(v2, v3, hw, lw);
        *reinterpret_cast<uint32_t*>(g_oh + i1) = hw;
        *reinterpret_cast<uint32_t*>(g_ol + i1) = lw;
    }
}

extern "C" void kernel_launch(void* const* d_in, const int* in_sizes, int n_in,
                              void* d_out, int out_size) {
    const float* x    = (const float*)d_in[0];
    const float* lns  = (const float*)d_in[1];
    const float* lnb  = (const float*)d_in[2];
    const float* Wq   = (const float*)d_in[3];
    const float* Wkv  = (const float*)d_in[4];
    const float* qns  = (const float*)d_in[5];
    const float* qnb  = (const float*)d_in[6];
    const float* kns  = (const float*)d_in[7];
    const float* knb  = (const float*)d_in[8];
    const float* Wout = (const float*)d_in[9];
    float* out = (float*)d_out;

    void *pxh, *pxl, *pq, *pkv, *poh, *pol, *pwq, *pwkv, *pwo;
    cudaGetSymbolAddress(&pxh, g_xn_hi);  cudaGetSymbolAddress(&pxl, g_xn_lo);
    cudaGetSymbolAddress(&pq,  g_q);      cudaGetSymbolAddress(&pkv, g_kv);
    cudaGetSymbolAddress(&poh, g_oh);     cudaGetSymbolAddress(&pol, g_ol);
    cudaGetSymbolAddress(&pwq, g_wq);
    cudaGetSymbolAddress(&pwkv, g_wkv);
    cudaGetSymbolAddress(&pwo, g_wo);

    cudaFuncSetAttribute(gemm_mma, cudaFuncAttributeMaxDynamicSharedMemorySize, G_SMEM);
    cudaFuncSetAttribute(attn_mma, cudaFuncAttributeMaxDynamicSharedMemorySize, A_SMEM);

    ln_kernel<<<ROWS, 256>>>(x, lns, lnb);
    wconv_kernel<<<dim3(INNER/32, DIM/32), 256>>>(Wq,   (__half*)pwq,  DIM, INNER);
    wconv_kernel<<<dim3(KVDIM/32, DIM/32), 256>>>(Wkv,  (__half*)pwkv, DIM, KVDIM);
    wconv_kernel<<<dim3(DIM/32, INNER/32), 256>>>(Wout, (__half*)pwo,  INNER, DIM);

    gemm_mma<<<dim3(INNER/128, ROWS/128), 256, G_SMEM>>>(
        (const __half*)pxh, (const __half*)pxl, (const __half*)pwq,
        (float*)pq, INNER, DIM);
    gemm_mma<<<dim3(KVDIM/128, ROWS/128), 256, G_SMEM>>>(
        (const __half*)pxh, (const __half*)pxl, (const __half*)pwkv,
        (float*)pkv, KVDIM, DIM);
    qkln_kernel<<<dim3(ROWS, 6), 128>>>(qns, qnb, kns, knb);
    attn_mma<<<dim3(SEQ/128, BATCH*HEADS), 256, A_SMEM>>>();
    gemm_mma<<<dim3(DIM/128, ROWS/128), 256, G_SMEM>>>(
        (const __half*)poh, (const __half*)pol, (const __half*)pwo,
        out, DIM, INNER);
}